// round 13
// baseline (speedup 1.0000x reference)
#include <cuda_runtime.h>
#include <cuda_bf16.h>
#include <cstdint>

// LSTMNet: B=1024, T=2048, H=64, NC=10
// 128-thread CTA processes TWO batch elements; weights in regs are SHARED
// between both streams (they depend only on the thread's rows, not batch).
// Thread (hid = t>>1, p = t&1): p=0 owns gate rows {i,f}, p=1 owns {g,o};
// both full 64-wide W_hh rows live in 64 packed u64 regs (128 f32).
// 2 CTAs/SM (reg cap 256/thread -> no spill), 4 recurrence streams per SM.
// Per step: 2x(16 LDS.128 + 64 FMA2) with cross-elem ILP, MUFU.TANH
// activations, gate exchange = shfl_xor(width=2). One __syncthreads per step
// covering both elements.

#define T_LEN 2048
#define HDIM  64
#define NCLS  10

#define FMA2(acc, a, b) \
    asm("fma.rn.f32x2 %0, %1, %2, %0;" : "+l"(acc) : "l"(a), "l"(b))
#define ADD2(d, a, b) \
    asm("add.rn.f32x2 %0, %1, %2;" : "=l"(d) : "l"(a), "l"(b))

__device__ __forceinline__ float tanh_fast(float z) {
    float r;
    asm("tanh.approx.f32 %0, %1;" : "=f"(r) : "f"(z));
    return r;
}

__device__ __forceinline__ float pair_sum(unsigned long long a) {
    return __uint_as_float((unsigned)a) + __uint_as_float((unsigned)(a >> 32));
}

__global__ __launch_bounds__(128, 2)
void lstm_net_kernel(const float* __restrict__ x,
                     const float* __restrict__ W_ih,
                     const float* __restrict__ W_hh,
                     const float* __restrict__ b_ih,
                     const float* __restrict__ b_hh,
                     const float* __restrict__ fc1_w,
                     const float* __restrict__ fc1_b,
                     const float* __restrict__ fc2_w,
                     const float* __restrict__ fc2_b,
                     float* __restrict__ out)
{
    __shared__ __align__(16) float sxA[T_LEN];     // elem A x row (8 KB)
    __shared__ __align__(16) float sxB[T_LEN];     // elem B x row (8 KB)
    __shared__ __align__(16) float shA[2][HDIM];   // double-buffered hidden, A
    __shared__ __align__(16) float shB[2][HDIM];   // double-buffered hidden, B
    __shared__ __align__(16) float s1A[HDIM];      // fc1 out A
    __shared__ __align__(16) float s1B[HDIM];      // fc1 out B

    const int bA  = 2 * blockIdx.x;
    const int bB  = bA + 1;
    const int t   = threadIdx.x;
    const int hid = t >> 1;
    const int p   = t & 1;
    const int r0  = (2 * p) * HDIM + hid;          // i (p=0) / g (p=1)
    const int r1  = (2 * p + 1) * HDIM + hid;      // f (p=0) / o (p=1)

    // ---- stage both x rows (coalesced float4) ----
    {
        const float4* xA = reinterpret_cast<const float4*>(x + (size_t)bA * T_LEN);
        const float4* xB = reinterpret_cast<const float4*>(x + (size_t)bB * T_LEN);
        float4* sA4 = reinterpret_cast<float4*>(sxA);
        float4* sB4 = reinterpret_cast<float4*>(sxB);
        #pragma unroll
        for (int i = t; i < T_LEN / 4; i += 128) { sA4[i] = xA[i]; sB4[i] = xB[i]; }
    }

    // ---- both full W_hh rows -> 64 packed u64 regs (shared by both streams) ----
    unsigned long long w0[32], w1[32];
    {
        const ulonglong2* p0 = reinterpret_cast<const ulonglong2*>(W_hh + (size_t)r0 * HDIM);
        const ulonglong2* p1 = reinterpret_cast<const ulonglong2*>(W_hh + (size_t)r1 * HDIM);
        #pragma unroll
        for (int j = 0; j < 16; j++) {
            ulonglong2 v0 = p0[j];
            w0[2 * j] = v0.x;  w0[2 * j + 1] = v0.y;
            ulonglong2 v1 = p1[j];
            w1[2 * j] = v1.x;  w1[2 * j + 1] = v1.y;
        }
    }
    const float w_in0 = W_ih[r0];
    const float w_in1 = W_ih[r1];
    const float bias0 = b_ih[r0] + b_hh[r0];
    const float bias1 = b_ih[r1] + b_hh[r1];

    // row0 activation: p=0 -> sigmoid (i), p=1 -> tanh (g). row1 always sigmoid.
    const float zs0 = p ? 1.0f : 0.5f;
    const float aa0 = p ? 1.0f : 0.5f;
    const float ab0 = p ? 0.0f : 0.5f;

    if (t < HDIM) { shA[0][t] = 0.0f; shB[0][t] = 0.0f; }
    float cA = 0.0f, cB = 0.0f;
    __syncthreads();

    // one LSTM step for BOTH elements: read sh*[RB], write sh*[RB^1]
    #define LSTM_STEP(RB, XTA, XTB)                                                  \
    {                                                                                \
        const ulonglong2* hpA = reinterpret_cast<const ulonglong2*>(shA[RB]);        \
        const ulonglong2* hpB = reinterpret_cast<const ulonglong2*>(shB[RB]);        \
        unsigned long long a00 = 0ull, a01 = 0ull, a10 = 0ull, a11 = 0ull;           \
        unsigned long long b00 = 0ull, b01 = 0ull, b10 = 0ull, b11 = 0ull;           \
        _Pragma("unroll")                                                            \
        for (int j = 0; j < 4; j++) {                                                \
            ulonglong2 hA0 = hpA[4 * j + 0], hA1 = hpA[4 * j + 1];                   \
            ulonglong2 hA2 = hpA[4 * j + 2], hA3 = hpA[4 * j + 3];                   \
            ulonglong2 hB0 = hpB[4 * j + 0], hB1 = hpB[4 * j + 1];                   \
            ulonglong2 hB2 = hpB[4 * j + 2], hB3 = hpB[4 * j + 3];                   \
            FMA2(a00, w0[8 * j + 0], hA0.x);  FMA2(b00, w0[8 * j + 0], hB0.x);       \
            FMA2(a10, w1[8 * j + 0], hA0.x);  FMA2(b10, w1[8 * j + 0], hB0.x);       \
            FMA2(a01, w0[8 * j + 1], hA0.y);  FMA2(b01, w0[8 * j + 1], hB0.y);       \
            FMA2(a11, w1[8 * j + 1], hA0.y);  FMA2(b11, w1[8 * j + 1], hB0.y);       \
            FMA2(a00, w0[8 * j + 2], hA1.x);  FMA2(b00, w0[8 * j + 2], hB1.x);       \
            FMA2(a10, w1[8 * j + 2], hA1.x);  FMA2(b10, w1[8 * j + 2], hB1.x);       \
            FMA2(a01, w0[8 * j + 3], hA1.y);  FMA2(b01, w0[8 * j + 3], hB1.y);       \
            FMA2(a11, w1[8 * j + 3], hA1.y);  FMA2(b11, w1[8 * j + 3], hB1.y);       \
            FMA2(a00, w0[8 * j + 4], hA2.x);  FMA2(b00, w0[8 * j + 4], hB2.x);       \
            FMA2(a10, w1[8 * j + 4], hA2.x);  FMA2(b10, w1[8 * j + 4], hB2.x);       \
            FMA2(a01, w0[8 * j + 5], hA2.y);  FMA2(b01, w0[8 * j + 5], hB2.y);       \
            FMA2(a11, w1[8 * j + 5], hA2.y);  FMA2(b11, w1[8 * j + 5], hB2.y);       \
            FMA2(a00, w0[8 * j + 6], hA3.x);  FMA2(b00, w0[8 * j + 6], hB3.x);       \
            FMA2(a10, w1[8 * j + 6], hA3.x);  FMA2(b10, w1[8 * j + 6], hB3.x);       \
            FMA2(a01, w0[8 * j + 7], hA3.y);  FMA2(b01, w0[8 * j + 7], hB3.y);       \
            FMA2(a11, w1[8 * j + 7], hA3.y);  FMA2(b11, w1[8 * j + 7], hB3.y);       \
        }                                                                            \
        unsigned long long sA0, sA1, sB0, sB1;                                       \
        ADD2(sA0, a00, a01);  ADD2(sA1, a10, a11);                                   \
        ADD2(sB0, b00, b01);  ADD2(sB1, b10, b11);                                   \
        float gA0 = fmaf((XTA), w_in0, bias0) + pair_sum(sA0);                       \
        float gA1 = fmaf((XTA), w_in1, bias1) + pair_sum(sA1);                       \
        float gB0 = fmaf((XTB), w_in0, bias0) + pair_sum(sB0);                       \
        float gB1 = fmaf((XTB), w_in1, bias1) + pair_sum(sB1);                       \
        float actA0 = fmaf(tanh_fast(gA0 * zs0), aa0, ab0);                          \
        float actA1 = fmaf(tanh_fast(gA1 * 0.5f), 0.5f, 0.5f);                       \
        float actB0 = fmaf(tanh_fast(gB0 * zs0), aa0, ab0);                          \
        float actB1 = fmaf(tanh_fast(gB1 * 0.5f), 0.5f, 0.5f);                       \
        float oA0 = __shfl_xor_sync(0xffffffffu, actA0, 1, 2);                       \
        float oA1 = __shfl_xor_sync(0xffffffffu, actA1, 1, 2);                       \
        float oB0 = __shfl_xor_sync(0xffffffffu, actB0, 1, 2);                       \
        float oB1 = __shfl_xor_sync(0xffffffffu, actB1, 1, 2);                       \
        float ivA = p ? oA0   : actA0;                                               \
        float fvA = p ? oA1   : actA1;                                               \
        float gvA = p ? actA0 : oA0;                                                 \
        float ovA = p ? actA1 : oA1;                                                 \
        float ivB = p ? oB0   : actB0;                                               \
        float fvB = p ? oB1   : actB1;                                               \
        float gvB = p ? actB0 : oB0;                                                 \
        float ovB = p ? actB1 : oB1;                                                 \
        cA = fmaf(fvA, cA, ivA * gvA);                                               \
        cB = fmaf(fvB, cB, ivB * gvB);                                               \
        float hnA = ovA * tanh_fast(cA);                                             \
        float hnB = ovB * tanh_fast(cB);                                             \
        if (p == 0) { shA[(RB) ^ 1][hid] = hnA; shB[(RB) ^ 1][hid] = hnB; }          \
        __syncthreads();                                                             \
    }

    #pragma unroll 1
    for (int step = 0; step < T_LEN; step += 4) {
        const float4 xvA = *reinterpret_cast<const float4*>(&sxA[step]);
        const float4 xvB = *reinterpret_cast<const float4*>(&sxB[step]);
        LSTM_STEP(0, xvA.x, xvB.x)
        LSTM_STEP(1, xvA.y, xvB.y)
        LSTM_STEP(0, xvA.z, xvB.z)
        LSTM_STEP(1, xvA.w, xvB.w)
    }
    #undef LSTM_STEP

    // T_LEN % 4 == 0: final h lives in buffer 0
    const float* hfA = shA[0];
    const float* hfB = shB[0];

    // ---- fc1 + relu: threads 0..63 do A, 64..127 do B ----
    if (t < HDIM) {
        float a = fc1_b[t];
        const float* wr = fc1_w + t * HDIM;
        #pragma unroll 16
        for (int k = 0; k < HDIM; k++) a = fmaf(wr[k], hfA[k], a);
        s1A[t] = fmaxf(a, 0.0f);
    } else {
        const int j = t - HDIM;
        float a = fc1_b[j];
        const float* wr = fc1_w + j * HDIM;
        #pragma unroll 16
        for (int k = 0; k < HDIM; k++) a = fmaf(wr[k], hfB[k], a);
        s1B[j] = fmaxf(a, 0.0f);
    }
    __syncthreads();

    // ---- fc2: threads 0..9 do A, 64..73 do B ----
    if (t < NCLS) {
        float a = fc2_b[t];
        const float* wr = fc2_w + t * HDIM;
        #pragma unroll 16
        for (int k = 0; k < HDIM; k++) a = fmaf(wr[k], s1A[k], a);
        out[(size_t)bA * NCLS + t] = a;
    } else if (t >= HDIM && t < HDIM + NCLS) {
        const int j = t - HDIM;
        float a = fc2_b[j];
        const float* wr = fc2_w + j * HDIM;
        #pragma unroll 16
        for (int k = 0; k < HDIM; k++) a = fmaf(wr[k], s1B[k], a);
        out[(size_t)bB * NCLS + j] = a;
    }
}

extern "C" void kernel_launch(void* const* d_in, const int* in_sizes, int n_in,
                              void* d_out, int out_size)
{
    const float* x     = (const float*)d_in[0];
    const float* W_ih  = (const float*)d_in[1];
    const float* W_hh  = (const float*)d_in[2];
    const float* b_ih  = (const float*)d_in[3];
    const float* b_hh  = (const float*)d_in[4];
    const float* fc1_w = (const float*)d_in[5];
    const float* fc1_b = (const float*)d_in[6];
    const float* fc2_w = (const float*)d_in[7];
    const float* fc2_b = (const float*)d_in[8];
    float* out = (float*)d_out;

    const int B = in_sizes[0] / T_LEN;   // 1024

    lstm_net_kernel<<<B / 2, 128>>>(x, W_ih, W_hh, b_ih, b_hh,
                                    fc1_w, fc1_b, fc2_w, fc2_b, out);
}

// round 14
// speedup vs baseline: 1.1425x; 1.1425x over previous
#include <cuda_runtime.h>
#include <cuda_bf16.h>
#include <cstdint>

// LSTMNet: B=1024, T=2048, H=64, NC=10
// 128-thread CTA per batch element, occupancy 3 (RF-max: ~165 regs).
// Thread (hid = t>>1, p = t&1): p=0 owns gate rows {i,f}, p=1 owns {g,o};
// both full 64-wide W_hh rows in 64 packed u64 regs.
// R13 changes vs R11:
//  - CTA phase-skew spin (blockIdx.x%3 -> 0/240/480 cyc) to de-convoy the 3
//    co-resident CTAs so tails overlap other CTAs' matvecs (148 % 3 == 1
//    makes co-resident bids {k,k+148,k+296} hit all three skew classes).
//  - sigmoid rows' weights/biases pre-scaled by 0.5 at load -> no mul before
//    MUFU.TANH in the per-step chain.
//  - input projection 'pre' folded into accumulator init -> no tail FADD.

#define T_LEN 2048
#define HDIM  64
#define NCLS  10

#define FMA2(acc, a, b) \
    asm("fma.rn.f32x2 %0, %1, %2, %0;" : "+l"(acc) : "l"(a), "l"(b))
#define ADD2(d, a, b) \
    asm("add.rn.f32x2 %0, %1, %2;" : "=l"(d) : "l"(a), "l"(b))
#define MUL2(d, a, b) \
    asm("mul.rn.f32x2 %0, %1, %2;" : "=l"(d) : "l"(a), "l"(b))

__device__ __forceinline__ float tanh_fast(float z) {
    float r;
    asm("tanh.approx.f32 %0, %1;" : "=f"(r) : "f"(z));
    return r;
}

__device__ __forceinline__ float pair_sum(unsigned long long a) {
    return __uint_as_float((unsigned)a) + __uint_as_float((unsigned)(a >> 32));
}

__device__ __forceinline__ unsigned long long pack_lo(float x) {
    return (unsigned long long)__float_as_uint(x);   // (x, 0.0f)
}

__global__ __launch_bounds__(128, 3)
void lstm_net_kernel(const float* __restrict__ x,
                     const float* __restrict__ W_ih,
                     const float* __restrict__ W_hh,
                     const float* __restrict__ b_ih,
                     const float* __restrict__ b_hh,
                     const float* __restrict__ fc1_w,
                     const float* __restrict__ fc1_b,
                     const float* __restrict__ fc2_w,
                     const float* __restrict__ fc2_b,
                     float* __restrict__ out)
{
    __shared__ __align__(16) float sx[T_LEN];      // x row (8 KB)
    __shared__ __align__(16) float sh[2][HDIM];    // double-buffered hidden
    __shared__ __align__(16) float s1[HDIM];       // fc1 out

    const int b   = blockIdx.x;
    const int t   = threadIdx.x;
    const int hid = t >> 1;
    const int p   = t & 1;
    const int r0  = (2 * p) * HDIM + hid;          // i (p=0) / g (p=1)
    const int r1  = (2 * p + 1) * HDIM + hid;      // f (p=0) / o (p=1)

    // ---- phase-skew spin: de-convoy the 3 co-resident CTAs ----
    {
        const int n = (int)(blockIdx.x % 3u) * 60;  // 0 / 60 / 120 dep FMAs
        float z = 1.0f;
        #pragma unroll 1
        for (int i = 0; i < n; i++) z = fmaf(z, 1.0000001f, 1e-7f);
        asm volatile("" :: "f"(z));
    }

    // ---- stage x[b,:] (coalesced float4) ----
    {
        const float4* xr = reinterpret_cast<const float4*>(x + (size_t)b * T_LEN);
        float4* sx4 = reinterpret_cast<float4*>(sx);
        #pragma unroll
        for (int i = t; i < T_LEN / 4; i += 128) sx4[i] = xr[i];
    }

    // ---- both full W_hh rows -> 64 packed u64 regs (128 f32) ----
    // Sigmoid rows (row0 when p==0; row1 always) pre-scaled by 0.5 so the
    // per-step activation is tanh_fast(gsum) directly.
    const float sc0 = p ? 1.0f : 0.5f;             // row0: tanh row (p=1) unscaled
    unsigned long long w0[32], w1[32];
    {
        unsigned long long h0s, h1s;
        {
            const unsigned u0 = __float_as_uint(sc0);
            const unsigned uh = __float_as_uint(0.5f);
            h0s = ((unsigned long long)u0 << 32) | u0;
            h1s = ((unsigned long long)uh << 32) | uh;
        }
        const ulonglong2* p0 = reinterpret_cast<const ulonglong2*>(W_hh + (size_t)r0 * HDIM);
        const ulonglong2* p1 = reinterpret_cast<const ulonglong2*>(W_hh + (size_t)r1 * HDIM);
        #pragma unroll
        for (int j = 0; j < 16; j++) {
            ulonglong2 v0 = p0[j];
            MUL2(w0[2 * j],     v0.x, h0s);
            MUL2(w0[2 * j + 1], v0.y, h0s);
            ulonglong2 v1 = p1[j];
            MUL2(w1[2 * j],     v1.x, h1s);
            MUL2(w1[2 * j + 1], v1.y, h1s);
        }
    }
    const float w_in0 = W_ih[r0] * sc0;
    const float w_in1 = W_ih[r1] * 0.5f;
    const float bias0 = (b_ih[r0] + b_hh[r0]) * sc0;
    const float bias1 = (b_ih[r1] + b_hh[r1]) * 0.5f;

    // row0 activation: p=0 -> sigmoid (i), p=1 -> tanh (g). row1 always sigmoid.
    const float aa0 = p ? 1.0f : 0.5f;
    const float ab0 = p ? 0.0f : 0.5f;

    if (t < HDIM) sh[0][t] = 0.0f;
    float c = 0.0f;
    __syncthreads();

    // one LSTM step: read sh[RB], write sh[RB^1]
    #define LSTM_STEP(RB, XT)                                                        \
    {                                                                                \
        const float pre0 = fmaf((XT), w_in0, bias0);                                 \
        const float pre1 = fmaf((XT), w_in1, bias1);                                 \
        const ulonglong2* hp = reinterpret_cast<const ulonglong2*>(sh[RB]);          \
        unsigned long long A0 = pack_lo(pre0), A1 = 0ull;                            \
        unsigned long long B0 = pack_lo(pre1), B1 = 0ull;                            \
        _Pragma("unroll")                                                            \
        for (int j = 0; j < 4; j++) {                                                \
            ulonglong2 h0 = hp[4 * j + 0], h1 = hp[4 * j + 1];                       \
            ulonglong2 h2 = hp[4 * j + 2], h3 = hp[4 * j + 3];                       \
            FMA2(A0, w0[8 * j + 0], h0.x);  FMA2(B0, w1[8 * j + 0], h0.x);           \
            FMA2(A1, w0[8 * j + 1], h0.y);  FMA2(B1, w1[8 * j + 1], h0.y);           \
            FMA2(A0, w0[8 * j + 2], h1.x);  FMA2(B0, w1[8 * j + 2], h1.x);           \
            FMA2(A1, w0[8 * j + 3], h1.y);  FMA2(B1, w1[8 * j + 3], h1.y);           \
            FMA2(A0, w0[8 * j + 4], h2.x);  FMA2(B0, w1[8 * j + 4], h2.x);           \
            FMA2(A1, w0[8 * j + 5], h2.y);  FMA2(B1, w1[8 * j + 5], h2.y);           \
            FMA2(A0, w0[8 * j + 6], h3.x);  FMA2(B0, w1[8 * j + 6], h3.x);           \
            FMA2(A1, w0[8 * j + 7], h3.y);  FMA2(B1, w1[8 * j + 7], h3.y);           \
        }                                                                            \
        unsigned long long As, Bs;                                                   \
        ADD2(As, A0, A1);  ADD2(Bs, B0, B1);                                         \
        float g0 = pair_sum(As);                                                     \
        float g1 = pair_sum(Bs);                                                     \
        float act0 = fmaf(tanh_fast(g0), aa0, ab0);                                  \
        float act1 = fmaf(tanh_fast(g1), 0.5f, 0.5f);                                \
        float othA = __shfl_xor_sync(0xffffffffu, act0, 1, 2);                       \
        float othB = __shfl_xor_sync(0xffffffffu, act1, 1, 2);                       \
        float iv = p ? othA : act0;                                                  \
        float fv = p ? othB : act1;                                                  \
        float gv = p ? act0 : othA;                                                  \
        float ov = p ? act1 : othB;                                                  \
        c = fmaf(fv, c, iv * gv);                                                    \
        float hnew = ov * tanh_fast(c);                                              \
        if (p == 0) sh[(RB) ^ 1][hid] = hnew;                                        \
        __syncthreads();                                                             \
    }

    #pragma unroll 1
    for (int step = 0; step < T_LEN; step += 4) {
        const float4 xv = *reinterpret_cast<const float4*>(&sx[step]);
        LSTM_STEP(0, xv.x)
        LSTM_STEP(1, xv.y)
        LSTM_STEP(0, xv.z)
        LSTM_STEP(1, xv.w)
    }
    #undef LSTM_STEP

    // T_LEN % 4 == 0: final h lives in sh[0]
    const float* hf = sh[0];

    // ---- fc1 + relu (64 threads) ----
    if (t < HDIM) {
        float a = fc1_b[t];
        const float* wr = fc1_w + t * HDIM;
        #pragma unroll 16
        for (int k = 0; k < HDIM; k++) a = fmaf(wr[k], hf[k], a);
        s1[t] = fmaxf(a, 0.0f);
    }
    __syncthreads();

    // ---- fc2 (10 threads) ----
    if (t < NCLS) {
        float a = fc2_b[t];
        const float* wr = fc2_w + t * HDIM;
        #pragma unroll 16
        for (int k = 0; k < HDIM; k++) a = fmaf(wr[k], s1[k], a);
        out[(size_t)b * NCLS + t] = a;
    }
}

extern "C" void kernel_launch(void* const* d_in, const int* in_sizes, int n_in,
                              void* d_out, int out_size)
{
    const float* x     = (const float*)d_in[0];
    const float* W_ih  = (const float*)d_in[1];
    const float* W_hh  = (const float*)d_in[2];
    const float* b_ih  = (const float*)d_in[3];
    const float* b_hh  = (const float*)d_in[4];
    const float* fc1_w = (const float*)d_in[5];
    const float* fc1_b = (const float*)d_in[6];
    const float* fc2_w = (const float*)d_in[7];
    const float* fc2_b = (const float*)d_in[8];
    float* out = (float*)d_out;

    const int B = in_sizes[0] / T_LEN;   // 1024

    lstm_net_kernel<<<B, 128>>>(x, W_ih, W_hh, b_ih, b_hh,
                                fc1_w, fc1_b, fc2_w, fc2_b, out);
}